// round 10
// baseline (speedup 1.0000x reference)
#include <cuda_runtime.h>
#include <cuda_bf16.h>
#include <cstdint>

// Problem constants
#define BB   8
#define CC   64
#define NN   4096
#define OO   128
#define KNN  20

#define RESP 132      // gathermax result tile pitch
#define AP   72       // bf16 smem tile pitch (144B; conflict-free ldmatrix)

// single dynamic-smem symbol shared by all kernels
extern __shared__ char smem_dyn[];

// ---------------- scratch (static device globals; no allocation) -------------
__device__ float g_xx[BB * NN];                         // ||x_j||^2
__device__ float g_Ut[CC * 256];                        // combined weights [c][o']
__device__ float g_GT[(size_t)BB * NN * OO];            // G^T: [b][j][o]
__device__ float g_HT[(size_t)BB * NN * OO];            // H^T: [b][i][o]
__device__ int   g_idx[(size_t)BB * NN * KNN];          // knn indices
__device__ __nv_bfloat16 g_xt_hi[(size_t)BB * NN * CC]; // x^T split hi: [b][j][c]
__device__ __nv_bfloat16 g_xt_lo[(size_t)BB * NN * CC]; // x^T split lo: [b][j][c]
__device__ float g_scores[(size_t)BB * NN * NN];        // per-CTA score scratch (256MB)

// ---------------- PTX helpers (base ISA only: ldmatrix + mma.sync) -----------
__device__ __forceinline__ uint32_t smem_u32(const void* p) {
    uint32_t a;
    asm("{ .reg .u64 t; cvta.to.shared.u64 t, %1; cvt.u32.u64 %0, t; }" : "=r"(a) : "l"(p));
    return a;
}
__device__ __forceinline__ void ldsm_x4(uint32_t* r, uint32_t addr) {
    asm volatile("ldmatrix.sync.aligned.m8n8.x4.shared.b16 {%0,%1,%2,%3}, [%4];"
                 : "=r"(r[0]), "=r"(r[1]), "=r"(r[2]), "=r"(r[3]) : "r"(addr));
}
__device__ __forceinline__ void mma16816(float* d, const uint32_t* a, const uint32_t* b) {
    asm volatile("mma.sync.aligned.m16n8k16.row.col.f32.bf16.bf16.f32 "
                 "{%0,%1,%2,%3}, {%4,%5,%6,%7}, {%8,%9}, {%0,%1,%2,%3};"
                 : "+f"(d[0]), "+f"(d[1]), "+f"(d[2]), "+f"(d[3])
                 : "r"(a[0]), "r"(a[1]), "r"(a[2]), "r"(a[3]), "r"(b[0]), "r"(b[1]));
}

// branch-free sorted-desc top-20 value insert (compare-exchange chain, 40 instr)
__device__ __forceinline__ void fm_ins20(float s, float (&v)[20]) {
#pragma unroll
    for (int q = 0; q < 20; ++q) {
        float mx = fmaxf(v[q], s);
        s = fminf(v[q], s);
        v[q] = mx;
    }
}

// ---------------- kernel 1: transpose + bf16 split + xx ----------------------
__global__ __launch_bounds__(256) void split_kernel(const float* __restrict__ x) {
    __shared__ float tile[64 * 68];
    __shared__ float part[64 * 4];
    int b = blockIdx.y, jbase = blockIdx.x * 64, t = threadIdx.x;
    const float* xb = x + (size_t)b * CC * NN;
    for (int k = t; k < 64 * 16; k += 256) {
        int c = k >> 4, p = k & 15;
        *(float4*)&tile[c * 68 + p * 4] = *(const float4*)&xb[c * NN + jbase + p * 4];
    }
    __syncthreads();
    int jl = t >> 2, g = t & 3;
    __nv_bfloat16 hi[16], lo[16];
    float ss = 0.f;
#pragma unroll
    for (int cc = 0; cc < 16; ++cc) {
        float v = tile[(g * 16 + cc) * 68 + jl];
        ss += v * v;
        __nv_bfloat16 h = __float2bfloat16(v);
        hi[cc] = h;
        lo[cc] = __float2bfloat16(v - __bfloat162float(h));
    }
    part[jl * 4 + g] = ss;
    size_t base = ((size_t)b * NN + jbase + jl) * CC + g * 16;
    *(uint4*)&g_xt_hi[base]     = *(uint4*)&hi[0];
    *(uint4*)&g_xt_hi[base + 8] = *(uint4*)&hi[8];
    *(uint4*)&g_xt_lo[base]     = *(uint4*)&lo[0];
    *(uint4*)&g_xt_lo[base + 8] = *(uint4*)&lo[8];
    __syncthreads();
    if (t < 64)
        g_xx[b * NN + jbase + t] = part[t * 4] + part[t * 4 + 1] + part[t * 4 + 2] + part[t * 4 + 3];
}

// ---------------- kernel 2: build combined weight Ut[c][o'] ------------------
__global__ void uprep_kernel(const float* __restrict__ W) {
    int c = blockIdx.x;
    int o = threadIdx.x;
    float v;
    if (o < OO) v = W[o * (2 * CC) + c];
    else {
        int oo = o - OO;
        v = W[oo * (2 * CC) + CC + c] - W[oo * (2 * CC) + c];
    }
    g_Ut[c * 256 + o] = v;
}

// ---------------- kernel 3: GH^T GEMM -> g_GT / g_HT -------------------------
__global__ __launch_bounds__(256) void gemm_gh_kernel(const float* __restrict__ x,
                                                      const float* __restrict__ bvec) {
    float* sm = (float*)smem_dyn;
    float* su = sm;                 // [64][256]
    float* sx = sm + CC * 256;      // [64][64]

    int b = blockIdx.y;
    int jbase = blockIdx.x * 64;
    int t = threadIdx.x;
    int tx = t & 7;
    int ty = t >> 3;

    const float4* ut4 = (const float4*)g_Ut;
    float4* su4 = (float4*)su;
    for (int k = t; k < CC * 256 / 4; k += 256) su4[k] = ut4[k];

    const float* xb = x + (size_t)b * CC * NN;
    for (int k = t; k < CC * 16; k += 256) {
        int c = k >> 4, p = k & 15;
        *(float4*)&sx[c * 64 + p * 4] = *(const float4*)&xb[c * NN + jbase + p * 4];
    }
    __syncthreads();

    float acc[8][8];
#pragma unroll
    for (int i = 0; i < 8; ++i)
#pragma unroll
        for (int j = 0; j < 8; ++j) acc[i][j] = 0.f;

#pragma unroll 4
    for (int c = 0; c < CC; ++c) {
        float4 a0 = *(float4*)&su[c * 256 + ty * 8];
        float4 a1 = *(float4*)&su[c * 256 + ty * 8 + 4];
        float4 b0 = *(float4*)&sx[c * 64 + tx * 8];
        float4 b1 = *(float4*)&sx[c * 64 + tx * 8 + 4];
        float aa[8] = {a0.x, a0.y, a0.z, a0.w, a1.x, a1.y, a1.z, a1.w};
        float bb[8] = {b0.x, b0.y, b0.z, b0.w, b1.x, b1.y, b1.z, b1.w};
#pragma unroll
        for (int i = 0; i < 8; ++i)
#pragma unroll
            for (int j = 0; j < 8; ++j) acc[i][j] += aa[i] * bb[j];
    }

    int obase = ty * 8;
    bool isH = (obase >= OO);
    float bias[8];
    if (isH) {
#pragma unroll
        for (int i = 0; i < 8; ++i) bias[i] = bvec[obase - OO + i];
    }
#pragma unroll
    for (int jq = 0; jq < 8; ++jq) {
        int j = jbase + tx * 8 + jq;
        float* dst = isH ? &g_HT[((size_t)b * NN + j) * OO + (obase - OO)]
                         : &g_GT[((size_t)b * NN + j) * OO + obase];
#pragma unroll
        for (int i = 0; i < 8; ++i) {
            float v = acc[i][jq];
            if (isH) v += bias[i];
            dst[i] = v;
        }
    }
}

// ---------------- kernel 4: HMMA distance GEMM + value-only top-20 -----------
// 256 threads (8 warps). Warp w: rows [16w,16w+16). j in 64-chunks, B double-buf.
// Pass 1: stream chunks; per-lane top-20 VALUES via FMNMX chain; all scores to
//         per-CTA global scratch.
// Pass 2: per-row thread merges the two half-lists -> exact 20th value, then
//         rescans its 2048 stored scores collecting indices (> first, == fill
//         in ascending-j order, matching stable top_k tie-breaking).
#define A_TILE (128 * AP * 2)            // 18432 bytes per A sub-tile
#define B_TILE (64 * AP * 2)             // 9216 bytes per B sub-tile
#define OFF_AHI 0
#define OFF_ALO A_TILE                   // 18432
#define OFF_B   (2 * A_TILE)             // 36864
#define B_BUF_STRIDE (2 * B_TILE)        // 18432 (hi at +0, lo at +B_TILE)
#define OFF_NXX (OFF_B + 2 * B_BUF_STRIDE)    // 73728 (2 bufs x 64 floats)
#define KNN_SMEM (OFF_NXX + 2 * 64 * 4)       // 74240 bytes

__device__ __forceinline__ void load_b_tile(char* sm, int b, int jbase, int buf, int t) {
    __nv_bfloat16* bh = (__nv_bfloat16*)(sm + OFF_B + buf * B_BUF_STRIDE);
    __nv_bfloat16* bl = (__nv_bfloat16*)(sm + OFF_B + buf * B_BUF_STRIDE + B_TILE);
    const uint4* srcH = (const uint4*)(g_xt_hi + ((size_t)b * NN + jbase) * CC);
    const uint4* srcL = (const uint4*)(g_xt_lo + ((size_t)b * NN + jbase) * CC);
#pragma unroll
    for (int it = 0; it < 2; ++it) {
        int k = t + it * 256;
        int row = k >> 3, p = k & 7;
        *(uint4*)&bh[row * AP + p * 8] = srcH[k];
        *(uint4*)&bl[row * AP + p * 8] = srcL[k];
    }
    if (t >= 64 && t < 128) {
        int r = t - 64;
        ((float*)(sm + OFF_NXX))[buf * 64 + r] = -g_xx[b * NN + jbase + r];
    }
}

__global__ __launch_bounds__(256, 2) void knn_kernel() {
    char* sm = smem_dyn;
    uint32_t sbase = smem_u32(sm);
    int t = threadIdx.x;
    int warp = t >> 5, lane = t & 31;
    int gid = lane >> 2, tig = lane & 3;
    int b = blockIdx.y;
    int ibase = blockIdx.x * 128;
    int cta = b * (NN / 128) + blockIdx.x;
    int mrow0 = warp * 16;

    __nv_bfloat16* sAhi = (__nv_bfloat16*)(sm + OFF_AHI);
    __nv_bfloat16* sAlo = (__nv_bfloat16*)(sm + OFF_ALO);
    float* nxx = (float*)(sm + OFF_NXX);

    // A data
    {
        const uint4* srcH = (const uint4*)(g_xt_hi + ((size_t)b * NN + ibase) * CC);
        const uint4* srcL = (const uint4*)(g_xt_lo + ((size_t)b * NN + ibase) * CC);
#pragma unroll
        for (int it = 0; it < 4; ++it) {
            int k = t + it * 256;
            int row = k >> 3, p = k & 7;
            *(uint4*)&sAhi[row * AP + p * 8] = srcH[k];
            *(uint4*)&sAlo[row * AP + p * 8] = srcL[k];
        }
    }
    load_b_tile(sm, b, 0, 0, t);   // preload chunk 0

    // per-lane top-20 values (sorted desc), no indices
    float v[20];
#pragma unroll
    for (int q = 0; q < 20; ++q) v[q] = -3.4e38f;

    // ldmatrix lane address components
    int arow = (lane & 7) + 8 * ((lane >> 3) & 1);
    int asel = 8 * (lane >> 4);
    int brow = ((lane >> 4) & 1) * 8 + (lane & 7);
    int bsel = 8 * ((lane >> 3) & 1);
    bool oddh = tig & 1;
    int colbase = 4 * (tig >> 1);
    int rloc = mrow0 + gid + 8 * (tig & 1);     // row this lane's candidates belong to
    float* srow_out = g_scores + ((size_t)cta * 128 + rloc) * NN;

    for (int ch = 0; ch < 64; ++ch) {
        __syncthreads();   // B[ch]+nxx[ch] ready; all warps done with iter ch-1
        int curb = ch & 1;
        if (ch < 63) load_b_tile(sm, b, (ch + 1) * 64, curb ^ 1, t);

        float acc[8][4];
#pragma unroll
        for (int nj = 0; nj < 8; ++nj)
#pragma unroll
            for (int q = 0; q < 4; ++q) acc[nj][q] = 0.f;

#pragma unroll
        for (int ks = 0; ks < 4; ++ks) {
            int kc = ks * 16;
            uint32_t ah[4], al[4];
            uint32_t aoff = sbase + OFF_AHI + ((mrow0 + arow) * AP + kc + asel) * 2;
            ldsm_x4(ah, aoff);
            ldsm_x4(al, aoff + A_TILE);
#pragma unroll
            for (int njp = 0; njp < 4; ++njp) {
                uint32_t bh4[4], bl4[4];
                uint32_t boff = sbase + OFF_B + curb * B_BUF_STRIDE
                              + ((njp * 16 + brow) * AP + kc + bsel) * 2;
                ldsm_x4(bh4, boff);
                ldsm_x4(bl4, boff + B_TILE);
                mma16816(acc[njp * 2], ah, bh4);
                mma16816(acc[njp * 2], ah, bl4);
                mma16816(acc[njp * 2], al, bh4);
                mma16816(acc[njp * 2], al, bl4);
                mma16816(acc[njp * 2 + 1], ah, bh4 + 2);
                mma16816(acc[njp * 2 + 1], ah, bl4 + 2);
                mma16816(acc[njp * 2 + 1], al, bh4 + 2);
                mma16816(acc[njp * 2 + 1], al, bl4 + 2);
            }
        }

        // fragment swap -> lane owns ONE row, 4 consecutive cols per nj
        const float* nxc = nxx + curb * 64;
#pragma unroll
        for (int nj = 0; nj < 8; ++nj) {
            float d0 = acc[nj][0], d1 = acc[nj][1], d2 = acc[nj][2], d3 = acc[nj][3];
            float r0 = __shfl_xor_sync(0xffffffffu, oddh ? d0 : d2, 1);
            float r1 = __shfl_xor_sync(0xffffffffu, oddh ? d1 : d3, 1);
            float c0 = oddh ? r0 : d0;
            float c1 = oddh ? r1 : d1;
            float c2 = oddh ? d2 : r0;
            float c3 = oddh ? d3 : r1;
            int jc = nj * 8 + colbase;
            float4 nx = *(const float4*)&nxc[jc];
            float s0 = fmaf(2.f, c0, nx.x);
            float s1 = fmaf(2.f, c1, nx.y);
            float s2 = fmaf(2.f, c2, nx.z);
            float s3 = fmaf(2.f, c3, nx.w);
            // store ALL scores to scratch (read back in pass 2)
            *(float4*)&srow_out[ch * 64 + jc] = make_float4(s0, s1, s2, s3);
            // group prefilter + branch-free value inserts
            float thr = v[19];
            float gmax = fmaxf(fmaxf(s0, s1), fmaxf(s2, s3));
            if (gmax > thr) {
                if (s0 > thr) fm_ins20(s0, v);
                if (s1 > v[19]) fm_ins20(s1, v);
                if (s2 > v[19]) fm_ins20(s2, v);
                if (s3 > v[19]) fm_ins20(s3, v);
            }
        }
    }

    __syncthreads();   // all MMA reads done -> overlay A region with half-lists
    {
        float* stv = (float*)sm;               // [128][40] floats (20480 B < A region)
        int half = tig >> 1;
        int base = rloc * 40 + half * 20;
#pragma unroll
        for (int q = 0; q < 20; ++q) stv[base + q] = v[q];
        __syncthreads();   // also fences the g_scores STGs for intra-CTA readers

        // pass 2: thread t (<128) owns row t
        if (t < 128) {
            // exact row 20th-largest from the two half-top-20 lists
            float v2[20];
#pragma unroll
            for (int q = 0; q < 20; ++q) v2[q] = -3.4e38f;
            const float* sl = stv + t * 40;
#pragma unroll
            for (int u = 0; u < 40; ++u) fm_ins20(sl[u], v2);
            float thr = v2[19];

            // rescan stored scores, collect indices
            int* gl = (int*)(sm + OFF_B) + t * 20;     // strictly-greater list (<=19)
            int* el = gl + 128 * 20;                    // equals list (cap 20)
            int cg = 0, ce = 0;
            const float* srow = g_scores + ((size_t)cta * 128 + t) * NN;
            for (int jj = 0; jj < NN; jj += 4) {
                float4 sv = *(const float4*)&srow[jj];
                float ss[4] = {sv.x, sv.y, sv.z, sv.w};
#pragma unroll
                for (int q = 0; q < 4; ++q) {
                    float s = ss[q];
                    if (s > thr) {
                        if (cg < 20) gl[cg++] = jj + q;
                    } else if (s == thr && ce < 20) {
                        el[ce++] = jj + q;
                    }
                }
            }
            int* dst = &g_idx[((size_t)b * NN + ibase + t) * KNN];
#pragma unroll
            for (int k = 0; k < KNN; ++k)
                dst[k] = (k < cg) ? gl[k] : el[k - cg];
        }
    }
}

// ---------------- kernel 5: gather-max + leaky + transposed write ------------
__global__ __launch_bounds__(256) void gathermax_kernel(float* __restrict__ out) {
    __shared__ int   sidx[32 * KNN];
    __shared__ float sres[32 * RESP];
    int b = blockIdx.y;
    int ibase = blockIdx.x * 32;
    int t = threadIdx.x;
    int w = t >> 5;
    int l = t & 31;

    for (int k = t; k < 32 * KNN; k += 256)
        sidx[k] = g_idx[((size_t)b * NN + ibase) * KNN + k];
    __syncthreads();

    const float* GTb = g_GT + (size_t)b * NN * OO;
    const float* HTb = g_HT + (size_t)b * NN * OO;

#pragma unroll
    for (int p = 0; p < 4; ++p) {
        int pp = w * 4 + p;
        int i = ibase + pp;
        float4 m = make_float4(-3.4e38f, -3.4e38f, -3.4e38f, -3.4e38f);
#pragma unroll
        for (int k = 0; k < KNN; ++k) {
            int j = sidx[pp * KNN + k];
            float4 g = *(const float4*)&GTb[(size_t)j * OO + l * 4];
            m.x = fmaxf(m.x, g.x); m.y = fmaxf(m.y, g.y);
            m.z = fmaxf(m.z, g.z); m.w = fmaxf(m.w, g.w);
        }
        float4 h = *(const float4*)&HTb[(size_t)i * OO + l * 4];
        float v0 = m.x + h.x, v1 = m.y + h.y, v2 = m.z + h.z, v3 = m.w + h.w;
        v0 = v0 >= 0.f ? v0 : 0.2f * v0;
        v1 = v1 >= 0.f ? v1 : 0.2f * v1;
        v2 = v2 >= 0.f ? v2 : 0.2f * v2;
        v3 = v3 >= 0.f ? v3 : 0.2f * v3;
        *(float4*)&sres[pp * RESP + l * 4] = make_float4(v0, v1, v2, v3);
    }
    __syncthreads();

    float* ob = out + (size_t)b * OO * NN;
    for (int k = t; k < OO * 32; k += 256) {
        int o = k >> 5, ii = k & 31;
        ob[(size_t)o * NN + ibase + ii] = sres[ii * RESP + o];
    }
}

// ---------------- launch ------------------------------------------------------
extern "C" void kernel_launch(void* const* d_in, const int* in_sizes, int n_in,
                              void* d_out, int out_size) {
    const float* x    = (const float*)d_in[0];   // (8, 64, 4096)
    const float* W    = (const float*)d_in[1];   // (128, 128)
    const float* bvec = (const float*)d_in[2];   // (128,)
    float* out = (float*)d_out;                  // (8, 128, 4096)

    const int SMEM_GEMM = (CC * 256 + CC * 64) * 4;   // 80KB
    cudaFuncSetAttribute(gemm_gh_kernel, cudaFuncAttributeMaxDynamicSharedMemorySize, SMEM_GEMM);
    cudaFuncSetAttribute(knn_kernel,     cudaFuncAttributeMaxDynamicSharedMemorySize, KNN_SMEM);

    split_kernel<<<dim3(NN / 64, BB), 256>>>(x);
    uprep_kernel<<<CC, 256>>>(W);
    gemm_gh_kernel<<<dim3(NN / 64, BB), 256, SMEM_GEMM>>>(x, bvec);
    knn_kernel<<<dim3(NN / 128, BB), 256, KNN_SMEM>>>();
    gathermax_kernel<<<dim3(NN / 32, BB), 256>>>(out);
}

// round 11
// speedup vs baseline: 1.0538x; 1.0538x over previous
#include <cuda_runtime.h>
#include <cuda_bf16.h>
#include <cstdint>

// Problem constants
#define BB   8
#define CC   64
#define NN   4096
#define OO   128
#define KNN  20

#define RESP 132      // gathermax result tile pitch
#define AP   72       // bf16 smem tile pitch (144B; conflict-free ldmatrix)

// single dynamic-smem symbol shared by all kernels
extern __shared__ char smem_dyn[];

// ---------------- scratch (static device globals; no allocation) -------------
__device__ float g_xx[BB * NN];                         // ||x_j||^2
__device__ float g_Ut[CC * 256];                        // combined weights [c][o']
__device__ float g_GT[(size_t)BB * NN * OO];            // G^T: [b][j][o]
__device__ float g_HT[(size_t)BB * NN * OO];            // H^T: [b][i][o]
__device__ int   g_idx[(size_t)BB * NN * KNN];          // knn indices
__device__ __nv_bfloat16 g_xt_hi[(size_t)BB * NN * CC]; // x^T split hi: [b][j][c]
__device__ __nv_bfloat16 g_xt_lo[(size_t)BB * NN * CC]; // x^T split lo: [b][j][c]

// ---------------- PTX helpers (base ISA only: ldmatrix + mma.sync) -----------
__device__ __forceinline__ uint32_t smem_u32(const void* p) {
    uint32_t a;
    asm("{ .reg .u64 t; cvta.to.shared.u64 t, %1; cvt.u32.u64 %0, t; }" : "=r"(a) : "l"(p));
    return a;
}
__device__ __forceinline__ void ldsm_x4(uint32_t* r, uint32_t addr) {
    asm volatile("ldmatrix.sync.aligned.m8n8.x4.shared.b16 {%0,%1,%2,%3}, [%4];"
                 : "=r"(r[0]), "=r"(r[1]), "=r"(r[2]), "=r"(r[3]) : "r"(addr));
}
__device__ __forceinline__ void mma16816(float* d, const uint32_t* a, const uint32_t* b) {
    asm volatile("mma.sync.aligned.m16n8k16.row.col.f32.bf16.bf16.f32 "
                 "{%0,%1,%2,%3}, {%4,%5,%6,%7}, {%8,%9}, {%0,%1,%2,%3};"
                 : "+f"(d[0]), "+f"(d[1]), "+f"(d[2]), "+f"(d[3])
                 : "r"(a[0]), "r"(a[1]), "r"(a[2]), "r"(a[3]), "r"(b[0]), "r"(b[1]));
}
#define BAR_SYNC(id, cnt)   asm volatile("bar.sync %0, %1;"   :: "r"(id), "r"(cnt) : "memory")
#define BAR_ARRIVE(id, cnt) asm volatile("bar.arrive %0, %1;" :: "r"(id), "r"(cnt) : "memory")

// sorted-desc register top-20 insert (caller guarantees s > v[19])
__device__ __forceinline__ void insert20(float s, int j, float (&v)[20], int (&ix)[20]) {
    bool c[20];
#pragma unroll
    for (int q = 0; q < 20; ++q) c[q] = s > v[q];
#pragma unroll
    for (int q = 19; q >= 1; --q) {
        if (c[q]) {
            v[q]  = c[q - 1] ? v[q - 1] : s;
            ix[q] = c[q - 1] ? ix[q - 1] : j;
        }
    }
    if (c[0]) { v[0] = s; ix[0] = j; }
}

// ---------------- kernel 1: transpose + bf16 split + xx ----------------------
__global__ __launch_bounds__(256) void split_kernel(const float* __restrict__ x) {
    __shared__ float tile[64 * 68];
    __shared__ float part[64 * 4];
    int b = blockIdx.y, jbase = blockIdx.x * 64, t = threadIdx.x;
    const float* xb = x + (size_t)b * CC * NN;
    for (int k = t; k < 64 * 16; k += 256) {
        int c = k >> 4, p = k & 15;
        *(float4*)&tile[c * 68 + p * 4] = *(const float4*)&xb[c * NN + jbase + p * 4];
    }
    __syncthreads();
    int jl = t >> 2, g = t & 3;
    __nv_bfloat16 hi[16], lo[16];
    float ss = 0.f;
#pragma unroll
    for (int cc = 0; cc < 16; ++cc) {
        float v = tile[(g * 16 + cc) * 68 + jl];
        ss += v * v;
        __nv_bfloat16 h = __float2bfloat16(v);
        hi[cc] = h;
        lo[cc] = __float2bfloat16(v - __bfloat162float(h));
    }
    part[jl * 4 + g] = ss;
    size_t base = ((size_t)b * NN + jbase + jl) * CC + g * 16;
    *(uint4*)&g_xt_hi[base]     = *(uint4*)&hi[0];
    *(uint4*)&g_xt_hi[base + 8] = *(uint4*)&hi[8];
    *(uint4*)&g_xt_lo[base]     = *(uint4*)&lo[0];
    *(uint4*)&g_xt_lo[base + 8] = *(uint4*)&lo[8];
    __syncthreads();
    if (t < 64)
        g_xx[b * NN + jbase + t] = part[t * 4] + part[t * 4 + 1] + part[t * 4 + 2] + part[t * 4 + 3];
}

// ---------------- kernel 2: build combined weight Ut[c][o'] ------------------
__global__ void uprep_kernel(const float* __restrict__ W) {
    int c = blockIdx.x;
    int o = threadIdx.x;
    float v;
    if (o < OO) v = W[o * (2 * CC) + c];
    else {
        int oo = o - OO;
        v = W[oo * (2 * CC) + CC + c] - W[oo * (2 * CC) + c];
    }
    g_Ut[c * 256 + o] = v;
}

// ---------------- kernel 3: GH^T GEMM -> g_GT / g_HT -------------------------
__global__ __launch_bounds__(256) void gemm_gh_kernel(const float* __restrict__ x,
                                                      const float* __restrict__ bvec) {
    float* sm = (float*)smem_dyn;
    float* su = sm;                 // [64][256]
    float* sx = sm + CC * 256;      // [64][64]

    int b = blockIdx.y;
    int jbase = blockIdx.x * 64;
    int t = threadIdx.x;
    int tx = t & 7;
    int ty = t >> 3;

    const float4* ut4 = (const float4*)g_Ut;
    float4* su4 = (float4*)su;
    for (int k = t; k < CC * 256 / 4; k += 256) su4[k] = ut4[k];

    const float* xb = x + (size_t)b * CC * NN;
    for (int k = t; k < CC * 16; k += 256) {
        int c = k >> 4, p = k & 15;
        *(float4*)&sx[c * 64 + p * 4] = *(const float4*)&xb[c * NN + jbase + p * 4];
    }
    __syncthreads();

    float acc[8][8];
#pragma unroll
    for (int i = 0; i < 8; ++i)
#pragma unroll
        for (int j = 0; j < 8; ++j) acc[i][j] = 0.f;

#pragma unroll 4
    for (int c = 0; c < CC; ++c) {
        float4 a0 = *(float4*)&su[c * 256 + ty * 8];
        float4 a1 = *(float4*)&su[c * 256 + ty * 8 + 4];
        float4 b0 = *(float4*)&sx[c * 64 + tx * 8];
        float4 b1 = *(float4*)&sx[c * 64 + tx * 8 + 4];
        float aa[8] = {a0.x, a0.y, a0.z, a0.w, a1.x, a1.y, a1.z, a1.w};
        float bb[8] = {b0.x, b0.y, b0.z, b0.w, b1.x, b1.y, b1.z, b1.w};
#pragma unroll
        for (int i = 0; i < 8; ++i)
#pragma unroll
            for (int j = 0; j < 8; ++j) acc[i][j] += aa[i] * bb[j];
    }

    int obase = ty * 8;
    bool isH = (obase >= OO);
    float bias[8];
    if (isH) {
#pragma unroll
        for (int i = 0; i < 8; ++i) bias[i] = bvec[obase - OO + i];
    }
#pragma unroll
    for (int jq = 0; jq < 8; ++jq) {
        int j = jbase + tx * 8 + jq;
        float* dst = isH ? &g_HT[((size_t)b * NN + j) * OO + (obase - OO)]
                         : &g_GT[((size_t)b * NN + j) * OO + obase];
#pragma unroll
        for (int i = 0; i < 8; ++i) {
            float v = acc[i][jq];
            if (isH) v += bias[i];
            dst[i] = v;
        }
    }
}

// ---------------- kernel 4: HMMA distance GEMM + register top-20 -------------
// 256 threads (8 warps). Warp w: rows [16w,16w+16). j in 64-chunks.
// 4-slot B pipeline with named producer/consumer barriers: warps decouple by
// up to ~3 chunks, absorbing per-warp drain variance.
// FULL_s = barrier id 1+s, EMPTY_s = 5+s, all count 512 (256 arrive + 256 sync).
#define A_TILE (128 * AP * 2)            // 18432 bytes per A sub-tile
#define B_TILE (64 * AP * 2)             // 9216 bytes per B sub-tile
#define OFF_AHI 0
#define OFF_ALO A_TILE                   // 18432
#define OFF_B   (2 * A_TILE)             // 36864
#define SLOT_STRIDE (2 * B_TILE)         // 18432 (hi at +0, lo at +B_TILE)
#define OFF_NXX (OFF_B + 4 * SLOT_STRIDE)     // 110592 (4 slots x 64 floats)
#define KNN_SMEM (OFF_NXX + 4 * 64 * 4)       // 111616 bytes

__device__ __forceinline__ void load_b_tile(char* sm, int b, int jbase, int slot, int t) {
    __nv_bfloat16* bh = (__nv_bfloat16*)(sm + OFF_B + slot * SLOT_STRIDE);
    __nv_bfloat16* bl = (__nv_bfloat16*)(sm + OFF_B + slot * SLOT_STRIDE + B_TILE);
    const uint4* srcH = (const uint4*)(g_xt_hi + ((size_t)b * NN + jbase) * CC);
    const uint4* srcL = (const uint4*)(g_xt_lo + ((size_t)b * NN + jbase) * CC);
#pragma unroll
    for (int it = 0; it < 2; ++it) {
        int k = t + it * 256;
        int row = k >> 3, p = k & 7;
        *(uint4*)&bh[row * AP + p * 8] = srcH[k];
        *(uint4*)&bl[row * AP + p * 8] = srcL[k];
    }
    if (t >= 64 && t < 128) {
        int r = t - 64;
        ((float*)(sm + OFF_NXX))[slot * 64 + r] = -g_xx[b * NN + jbase + r];
    }
}

__global__ __launch_bounds__(256, 2) void knn_kernel() {
    char* sm = smem_dyn;
    uint32_t sbase = smem_u32(sm);
    int t = threadIdx.x;
    int warp = t >> 5, lane = t & 31;
    int gid = lane >> 2, tig = lane & 3;
    int b = blockIdx.y;
    int ibase = blockIdx.x * 128;
    int mrow0 = warp * 16;

    __nv_bfloat16* sAhi = (__nv_bfloat16*)(sm + OFF_AHI);
    __nv_bfloat16* sAlo = (__nv_bfloat16*)(sm + OFF_ALO);
    float* nxx = (float*)(sm + OFF_NXX);

    // A data
    {
        const uint4* srcH = (const uint4*)(g_xt_hi + ((size_t)b * NN + ibase) * CC);
        const uint4* srcL = (const uint4*)(g_xt_lo + ((size_t)b * NN + ibase) * CC);
#pragma unroll
        for (int it = 0; it < 4; ++it) {
            int k = t + it * 256;
            int row = k >> 3, p = k & 7;
            *(uint4*)&sAhi[row * AP + p * 8] = srcH[k];
            *(uint4*)&sAlo[row * AP + p * 8] = srcL[k];
        }
    }
    // prologue: fill slots 0..2 (chunks 0..2), arrive FULL; pre-arm EMPTY_3
#pragma unroll
    for (int s = 0; s < 3; ++s) {
        load_b_tile(sm, b, s * 64, s, t);
        BAR_ARRIVE(1 + s, 512);
    }
    BAR_ARRIVE(5 + 3, 512);

    // register top-20 (sorted desc) + local pending stack
    float v[20]; int ixr[20];
#pragma unroll
    for (int q = 0; q < 20; ++q) { v[q] = -3.4e38f; ixr[q] = 0; }
    float pend_s[40]; int pend_j[40]; int cnt = 0;

    // ldmatrix lane address components
    int arow = (lane & 7) + 8 * ((lane >> 3) & 1);
    int asel = 8 * (lane >> 4);
    int brow = ((lane >> 4) & 1) * 8 + (lane & 7);
    int bsel = 8 * ((lane >> 3) & 1);
    bool oddh = tig & 1;
    int colbase = 4 * (tig >> 1);

    for (int ch = 0; ch < 64; ++ch) {
        int slot = ch & 3;
        BAR_SYNC(1 + slot, 512);        // wait B[ch] full (also fences A on ch=0)

        float acc[8][4];
#pragma unroll
        for (int nj = 0; nj < 8; ++nj)
#pragma unroll
            for (int q = 0; q < 4; ++q) acc[nj][q] = 0.f;

#pragma unroll
        for (int ks = 0; ks < 4; ++ks) {
            int kc = ks * 16;
            uint32_t ah[4], al[4];
            uint32_t aoff = sbase + OFF_AHI + ((mrow0 + arow) * AP + kc + asel) * 2;
            ldsm_x4(ah, aoff);
            ldsm_x4(al, aoff + A_TILE);
#pragma unroll
            for (int njp = 0; njp < 4; ++njp) {
                uint32_t bh4[4], bl4[4];
                uint32_t boff = sbase + OFF_B + slot * SLOT_STRIDE
                              + ((njp * 16 + brow) * AP + kc + bsel) * 2;
                ldsm_x4(bh4, boff);
                ldsm_x4(bl4, boff + B_TILE);
                mma16816(acc[njp * 2], ah, bh4);
                mma16816(acc[njp * 2], ah, bl4);
                mma16816(acc[njp * 2], al, bh4);
                mma16816(acc[njp * 2], al, bl4);
                mma16816(acc[njp * 2 + 1], ah, bh4 + 2);
                mma16816(acc[njp * 2 + 1], ah, bl4 + 2);
                mma16816(acc[njp * 2 + 1], al, bh4 + 2);
                mma16816(acc[njp * 2 + 1], al, bl4 + 2);
            }
        }

        // row-pair shared threshold (provably selection-preserving)
        float thr = v[19];
        thr = fmaxf(thr, __shfl_xor_sync(0xffffffffu, thr, 2));
        const float* nxc = nxx + slot * 64;
        // copy nxx for this lane's columns BEFORE releasing the slot
        float4 nxq[8];
#pragma unroll
        for (int nj = 0; nj < 8; ++nj)
            nxq[nj] = *(const float4*)&nxc[nj * 8 + colbase];

        // fragment swap -> lane owns ONE row, 4 consecutive cols per nj
        float sres[8][4];
#pragma unroll
        for (int nj = 0; nj < 8; ++nj) {
            float d0 = acc[nj][0], d1 = acc[nj][1], d2 = acc[nj][2], d3 = acc[nj][3];
            float r0 = __shfl_xor_sync(0xffffffffu, oddh ? d0 : d2, 1);
            float r1 = __shfl_xor_sync(0xffffffffu, oddh ? d1 : d3, 1);
            sres[nj][0] = fmaf(2.f, oddh ? r0 : d0, nxq[nj].x);
            sres[nj][1] = fmaf(2.f, oddh ? r1 : d1, nxq[nj].y);
            sres[nj][2] = fmaf(2.f, oddh ? d2 : r0, nxq[nj].z);
            sres[nj][3] = fmaf(2.f, oddh ? d3 : r1, nxq[nj].w);
        }

        BAR_ARRIVE(5 + slot, 512);      // release slot (all smem reads done)

        // filter + push (slot-independent from here)
#pragma unroll
        for (int nj = 0; nj < 8; ++nj) {
            float s0 = sres[nj][0], s1 = sres[nj][1], s2 = sres[nj][2], s3 = sres[nj][3];
            float gmax = fmaxf(fmaxf(s0, s1), fmaxf(s2, s3));
            if (gmax > thr) {
                int j0 = ch * 64 + nj * 8 + colbase;
                if (s0 > thr) { pend_s[cnt] = s0; pend_j[cnt] = j0;     ++cnt; }
                if (s1 > thr) { pend_s[cnt] = s1; pend_j[cnt] = j0 + 1; ++cnt; }
                if (s2 > thr) { pend_s[cnt] = s2; pend_j[cnt] = j0 + 2; ++cnt; }
                if (s3 > thr) { pend_s[cnt] = s3; pend_j[cnt] = j0 + 3; ++cnt; }
            }
        }
        if (cnt >= 8) {
            for (int u = 0; u < cnt; ++u) {
                float s = pend_s[u];
                if (s > v[19]) insert20(s, pend_j[u], v, ixr);
            }
            cnt = 0;
        }

        // produce chunk ch+3 into its slot
        if (ch + 3 < 64) {
            int ns = (ch + 3) & 3;
            BAR_SYNC(5 + ns, 512);       // wait slot empty
            load_b_tile(sm, b, (ch + 3) * 64, ns, t);
            BAR_ARRIVE(1 + ns, 512);     // mark full
        }
    }
    // final drain
    for (int u = 0; u < cnt; ++u) {
        float s = pend_s[u];
        if (s > v[19]) insert20(s, pend_j[u], v, ixr);
    }

    __syncthreads();   // all warps done -> overlay A (stv) and B (sti) regions
    {
        float* stv = (float*)sm;               // [128][43] floats (22016 B in A region)
        int*   sti = (int*)(sm + OFF_B);       // [128][43] ints  (22016 B in B region)
        int rloc = mrow0 + gid + 8 * (tig & 1);
        int half = tig >> 1;
        int base = rloc * 43 + half * 21;
#pragma unroll
        for (int q = 0; q < 20; ++q) { stv[base + q] = v[q]; sti[base + q] = ixr[q]; }
        stv[base + 20] = -3.4e38f;             // sentinel at 20 / 41
        __syncthreads();

        if (t < 128) {
            const float* a = stv + t * 43;
            const int*  ai = sti + t * 43;
            int ia = 0, ib = 21;
            int* dst = &g_idx[((size_t)b * NN + ibase + t) * KNN];
#pragma unroll
            for (int k = 0; k < KNN; ++k) {
                float va = a[ia], vb = a[ib];
                bool ta = va >= vb;
                dst[k] = ta ? ai[ia] : ai[ib];
                ia += ta;
                ib += !ta;
            }
        }
    }
}

// ---------------- kernel 5: gather-max + leaky + transposed write ------------
__global__ __launch_bounds__(256) void gathermax_kernel(float* __restrict__ out) {
    __shared__ int   sidx[32 * KNN];
    __shared__ float sres[32 * RESP];
    int b = blockIdx.y;
    int ibase = blockIdx.x * 32;
    int t = threadIdx.x;
    int w = t >> 5;
    int l = t & 31;

    for (int k = t; k < 32 * KNN; k += 256)
        sidx[k] = g_idx[((size_t)b * NN + ibase) * KNN + k];
    __syncthreads();

    const float* GTb = g_GT + (size_t)b * NN * OO;
    const float* HTb = g_HT + (size_t)b * NN * OO;

#pragma unroll
    for (int p = 0; p < 4; ++p) {
        int pp = w * 4 + p;
        int i = ibase + pp;
        float4 m = make_float4(-3.4e38f, -3.4e38f, -3.4e38f, -3.4e38f);
#pragma unroll
        for (int k = 0; k < KNN; ++k) {
            int j = sidx[pp * KNN + k];
            float4 g = *(const float4*)&GTb[(size_t)j * OO + l * 4];
            m.x = fmaxf(m.x, g.x); m.y = fmaxf(m.y, g.y);
            m.z = fmaxf(m.z, g.z); m.w = fmaxf(m.w, g.w);
        }
        float4 h = *(const float4*)&HTb[(size_t)i * OO + l * 4];
        float v0 = m.x + h.x, v1 = m.y + h.y, v2 = m.z + h.z, v3 = m.w + h.w;
        v0 = v0 >= 0.f ? v0 : 0.2f * v0;
        v1 = v1 >= 0.f ? v1 : 0.2f * v1;
        v2 = v2 >= 0.f ? v2 : 0.2f * v2;
        v3 = v3 >= 0.f ? v3 : 0.2f * v3;
        *(float4*)&sres[pp * RESP + l * 4] = make_float4(v0, v1, v2, v3);
    }
    __syncthreads();

    float* ob = out + (size_t)b * OO * NN;
    for (int k = t; k < OO * 32; k += 256) {
        int o = k >> 5, ii = k & 31;
        ob[(size_t)o * NN + ibase + ii] = sres[ii * RESP + o];
    }
}

// ---------------- launch ------------------------------------------------------
extern "C" void kernel_launch(void* const* d_in, const int* in_sizes, int n_in,
                              void* d_out, int out_size) {
    const float* x    = (const float*)d_in[0];   // (8, 64, 4096)
    const float* W    = (const float*)d_in[1];   // (128, 128)
    const float* bvec = (const float*)d_in[2];   // (128,)
    float* out = (float*)d_out;                  // (8, 128, 4096)

    const int SMEM_GEMM = (CC * 256 + CC * 64) * 4;   // 80KB
    cudaFuncSetAttribute(gemm_gh_kernel, cudaFuncAttributeMaxDynamicSharedMemorySize, SMEM_GEMM);
    cudaFuncSetAttribute(knn_kernel,     cudaFuncAttributeMaxDynamicSharedMemorySize, KNN_SMEM);

    split_kernel<<<dim3(NN / 64, BB), 256>>>(x);
    uprep_kernel<<<CC, 256>>>(W);
    gemm_gh_kernel<<<dim3(NN / 64, BB), 256, SMEM_GEMM>>>(x, bvec);
    knn_kernel<<<dim3(NN / 128, BB), 256, KNN_SMEM>>>();
    gathermax_kernel<<<dim3(NN / 32, BB), 256>>>(out);
}

// round 12
// speedup vs baseline: 1.3239x; 1.2563x over previous
#include <cuda_runtime.h>
#include <cuda_bf16.h>
#include <cstdint>

// Problem constants
#define BB   8
#define CC   64
#define NN   4096
#define OO   128
#define KNN  20

#define RESP 132      // gathermax result tile pitch
#define AP   72       // bf16 smem tile pitch (144B; conflict-free ldmatrix)

// single dynamic-smem symbol shared by all kernels
extern __shared__ char smem_dyn[];

// ---------------- scratch (static device globals; no allocation) -------------
__device__ float g_xx[BB * NN];                         // ||x_j||^2
__device__ float g_Ut[CC * 256];                        // combined weights [c][o']
__device__ float g_GT[(size_t)BB * NN * OO];            // G^T: [b][j][o]
__device__ float g_HT[(size_t)BB * NN * OO];            // H^T: [b][i][o]
__device__ int   g_idx[(size_t)BB * NN * KNN];          // knn indices
__device__ __nv_bfloat16 g_xt_hi[(size_t)BB * NN * CC]; // x^T split hi: [b][j][c]
__device__ __nv_bfloat16 g_xt_lo[(size_t)BB * NN * CC]; // x^T split lo: [b][j][c]

// ---------------- PTX helpers (base ISA only: ldmatrix + mma.sync) -----------
__device__ __forceinline__ uint32_t smem_u32(const void* p) {
    uint32_t a;
    asm("{ .reg .u64 t; cvta.to.shared.u64 t, %1; cvt.u32.u64 %0, t; }" : "=r"(a) : "l"(p));
    return a;
}
__device__ __forceinline__ void ldsm_x4(uint32_t* r, uint32_t addr) {
    asm volatile("ldmatrix.sync.aligned.m8n8.x4.shared.b16 {%0,%1,%2,%3}, [%4];"
                 : "=r"(r[0]), "=r"(r[1]), "=r"(r[2]), "=r"(r[3]) : "r"(addr));
}
__device__ __forceinline__ void mma16816(float* d, const uint32_t* a, const uint32_t* b) {
    asm volatile("mma.sync.aligned.m16n8k16.row.col.f32.bf16.bf16.f32 "
                 "{%0,%1,%2,%3}, {%4,%5,%6,%7}, {%8,%9}, {%0,%1,%2,%3};"
                 : "+f"(d[0]), "+f"(d[1]), "+f"(d[2]), "+f"(d[3])
                 : "r"(a[0]), "r"(a[1]), "r"(a[2]), "r"(a[3]), "r"(b[0]), "r"(b[1]));
}

// sorted-desc register top-20 insert (caller guarantees s > v[19])
__device__ __forceinline__ void insert20(float s, int j, float (&v)[20], int (&ix)[20]) {
    bool c[20];
#pragma unroll
    for (int q = 0; q < 20; ++q) c[q] = s > v[q];
#pragma unroll
    for (int q = 19; q >= 1; --q) {
        if (c[q]) {
            v[q]  = c[q - 1] ? v[q - 1] : s;
            ix[q] = c[q - 1] ? ix[q - 1] : j;
        }
    }
    if (c[0]) { v[0] = s; ix[0] = j; }
}

// ---------------- kernel 1: transpose + bf16 split + xx ----------------------
__global__ __launch_bounds__(256) void split_kernel(const float* __restrict__ x) {
    __shared__ float tile[64 * 68];
    __shared__ float part[64 * 4];
    int b = blockIdx.y, jbase = blockIdx.x * 64, t = threadIdx.x;
    const float* xb = x + (size_t)b * CC * NN;
    for (int k = t; k < 64 * 16; k += 256) {
        int c = k >> 4, p = k & 15;
        *(float4*)&tile[c * 68 + p * 4] = *(const float4*)&xb[c * NN + jbase + p * 4];
    }
    __syncthreads();
    int jl = t >> 2, g = t & 3;
    __nv_bfloat16 hi[16], lo[16];
    float ss = 0.f;
#pragma unroll
    for (int cc = 0; cc < 16; ++cc) {
        float v = tile[(g * 16 + cc) * 68 + jl];
        ss += v * v;
        __nv_bfloat16 h = __float2bfloat16(v);
        hi[cc] = h;
        lo[cc] = __float2bfloat16(v - __bfloat162float(h));
    }
    part[jl * 4 + g] = ss;
    size_t base = ((size_t)b * NN + jbase + jl) * CC + g * 16;
    *(uint4*)&g_xt_hi[base]     = *(uint4*)&hi[0];
    *(uint4*)&g_xt_hi[base + 8] = *(uint4*)&hi[8];
    *(uint4*)&g_xt_lo[base]     = *(uint4*)&lo[0];
    *(uint4*)&g_xt_lo[base + 8] = *(uint4*)&lo[8];
    __syncthreads();
    if (t < 64)
        g_xx[b * NN + jbase + t] = part[t * 4] + part[t * 4 + 1] + part[t * 4 + 2] + part[t * 4 + 3];
}

// ---------------- kernel 2: build combined weight Ut[c][o'] ------------------
__global__ void uprep_kernel(const float* __restrict__ W) {
    int c = blockIdx.x;
    int o = threadIdx.x;
    float v;
    if (o < OO) v = W[o * (2 * CC) + c];
    else {
        int oo = o - OO;
        v = W[oo * (2 * CC) + CC + c] - W[oo * (2 * CC) + c];
    }
    g_Ut[c * 256 + o] = v;
}

// ---------------- kernel 3: GH^T GEMM -> g_GT / g_HT -------------------------
__global__ __launch_bounds__(256) void gemm_gh_kernel(const float* __restrict__ x,
                                                      const float* __restrict__ bvec) {
    float* sm = (float*)smem_dyn;
    float* su = sm;                 // [64][256]
    float* sx = sm + CC * 256;      // [64][64]

    int b = blockIdx.y;
    int jbase = blockIdx.x * 64;
    int t = threadIdx.x;
    int tx = t & 7;
    int ty = t >> 3;

    const float4* ut4 = (const float4*)g_Ut;
    float4* su4 = (float4*)su;
    for (int k = t; k < CC * 256 / 4; k += 256) su4[k] = ut4[k];

    const float* xb = x + (size_t)b * CC * NN;
    for (int k = t; k < CC * 16; k += 256) {
        int c = k >> 4, p = k & 15;
        *(float4*)&sx[c * 64 + p * 4] = *(const float4*)&xb[c * NN + jbase + p * 4];
    }
    __syncthreads();

    float acc[8][8];
#pragma unroll
    for (int i = 0; i < 8; ++i)
#pragma unroll
        for (int j = 0; j < 8; ++j) acc[i][j] = 0.f;

#pragma unroll 4
    for (int c = 0; c < CC; ++c) {
        float4 a0 = *(float4*)&su[c * 256 + ty * 8];
        float4 a1 = *(float4*)&su[c * 256 + ty * 8 + 4];
        float4 b0 = *(float4*)&sx[c * 64 + tx * 8];
        float4 b1 = *(float4*)&sx[c * 64 + tx * 8 + 4];
        float aa[8] = {a0.x, a0.y, a0.z, a0.w, a1.x, a1.y, a1.z, a1.w};
        float bb[8] = {b0.x, b0.y, b0.z, b0.w, b1.x, b1.y, b1.z, b1.w};
#pragma unroll
        for (int i = 0; i < 8; ++i)
#pragma unroll
            for (int j = 0; j < 8; ++j) acc[i][j] += aa[i] * bb[j];
    }

    int obase = ty * 8;
    bool isH = (obase >= OO);
    float bias[8];
    if (isH) {
#pragma unroll
        for (int i = 0; i < 8; ++i) bias[i] = bvec[obase - OO + i];
    }
#pragma unroll
    for (int jq = 0; jq < 8; ++jq) {
        int j = jbase + tx * 8 + jq;
        float* dst = isH ? &g_HT[((size_t)b * NN + j) * OO + (obase - OO)]
                         : &g_GT[((size_t)b * NN + j) * OO + obase];
#pragma unroll
        for (int i = 0; i < 8; ++i) {
            float v = acc[i][jq];
            if (isH) v += bias[i];
            dst[i] = v;
        }
    }
}

// ---------------- kernel 4: HMMA distance GEMM + register top-20 -------------
// 256 threads (8 warps). Warp w: rows [16w,16w+16). j in 64-chunks, B double-buf.
// K=64, 4-term bf16 split, EXACT fp32 xx subtraction at filter time.
// R12 = R8 + row-pair shared threshold (lanes l, l^2 own the same row; using
// max of both lanes' 20th values is provably selection-preserving).
#define A_TILE (128 * AP * 2)            // 18432 bytes per A sub-tile
#define B_TILE (64 * AP * 2)             // 9216 bytes per B sub-tile
#define OFF_AHI 0
#define OFF_ALO A_TILE                   // 18432
#define OFF_B   (2 * A_TILE)             // 36864
#define B_BUF_STRIDE (2 * B_TILE)        // 18432 (hi at +0, lo at +B_TILE)
#define OFF_NXX (OFF_B + 2 * B_BUF_STRIDE)    // 73728 (2 bufs x 64 floats)
#define KNN_SMEM (OFF_NXX + 2 * 64 * 4)       // 74240 bytes

__device__ __forceinline__ void load_b_tile(char* sm, int b, int jbase, int buf, int t) {
    __nv_bfloat16* bh = (__nv_bfloat16*)(sm + OFF_B + buf * B_BUF_STRIDE);
    __nv_bfloat16* bl = (__nv_bfloat16*)(sm + OFF_B + buf * B_BUF_STRIDE + B_TILE);
    const uint4* srcH = (const uint4*)(g_xt_hi + ((size_t)b * NN + jbase) * CC);
    const uint4* srcL = (const uint4*)(g_xt_lo + ((size_t)b * NN + jbase) * CC);
#pragma unroll
    for (int it = 0; it < 2; ++it) {
        int k = t + it * 256;
        int row = k >> 3, p = k & 7;
        *(uint4*)&bh[row * AP + p * 8] = srcH[k];
        *(uint4*)&bl[row * AP + p * 8] = srcL[k];
    }
    if (t >= 64 && t < 128) {
        int r = t - 64;
        ((float*)(sm + OFF_NXX))[buf * 64 + r] = -g_xx[b * NN + jbase + r];
    }
}

__global__ __launch_bounds__(256, 2) void knn_kernel() {
    char* sm = smem_dyn;
    uint32_t sbase = smem_u32(sm);
    int t = threadIdx.x;
    int warp = t >> 5, lane = t & 31;
    int gid = lane >> 2, tig = lane & 3;
    int b = blockIdx.y;
    int ibase = blockIdx.x * 128;
    int mrow0 = warp * 16;

    __nv_bfloat16* sAhi = (__nv_bfloat16*)(sm + OFF_AHI);
    __nv_bfloat16* sAlo = (__nv_bfloat16*)(sm + OFF_ALO);
    float* nxx = (float*)(sm + OFF_NXX);

    // A data
    {
        const uint4* srcH = (const uint4*)(g_xt_hi + ((size_t)b * NN + ibase) * CC);
        const uint4* srcL = (const uint4*)(g_xt_lo + ((size_t)b * NN + ibase) * CC);
#pragma unroll
        for (int it = 0; it < 4; ++it) {
            int k = t + it * 256;
            int row = k >> 3, p = k & 7;
            *(uint4*)&sAhi[row * AP + p * 8] = srcH[k];
            *(uint4*)&sAlo[row * AP + p * 8] = srcL[k];
        }
    }
    load_b_tile(sm, b, 0, 0, t);   // preload chunk 0

    // register top-20 (sorted desc) + local pending stack
    float v[20]; int ixr[20];
#pragma unroll
    for (int q = 0; q < 20; ++q) { v[q] = -3.4e38f; ixr[q] = 0; }
    float pend_s[40]; int pend_j[40]; int cnt = 0;

    // ldmatrix lane address components
    int arow = (lane & 7) + 8 * ((lane >> 3) & 1);
    int asel = 8 * (lane >> 4);
    int brow = ((lane >> 4) & 1) * 8 + (lane & 7);
    int bsel = 8 * ((lane >> 3) & 1);
    bool oddh = tig & 1;
    int colbase = 4 * (tig >> 1);

    for (int ch = 0; ch < 64; ++ch) {
        __syncthreads();   // B[ch]+nxx[ch] ready; all warps done with iter ch-1
        int curb = ch & 1;
        if (ch < 63) load_b_tile(sm, b, (ch + 1) * 64, curb ^ 1, t);

        float acc[8][4];
#pragma unroll
        for (int nj = 0; nj < 8; ++nj)
#pragma unroll
            for (int q = 0; q < 4; ++q) acc[nj][q] = 0.f;

#pragma unroll
        for (int ks = 0; ks < 4; ++ks) {
            int kc = ks * 16;
            uint32_t ah[4], al[4];
            uint32_t aoff = sbase + OFF_AHI + ((mrow0 + arow) * AP + kc + asel) * 2;
            ldsm_x4(ah, aoff);
            ldsm_x4(al, aoff + A_TILE);
#pragma unroll
            for (int njp = 0; njp < 4; ++njp) {
                uint32_t bh4[4], bl4[4];
                uint32_t boff = sbase + OFF_B + curb * B_BUF_STRIDE
                              + ((njp * 16 + brow) * AP + kc + bsel) * 2;
                ldsm_x4(bh4, boff);
                ldsm_x4(bl4, boff + B_TILE);
                mma16816(acc[njp * 2], ah, bh4);
                mma16816(acc[njp * 2], ah, bl4);
                mma16816(acc[njp * 2], al, bh4);
                mma16816(acc[njp * 2], al, bl4);
                mma16816(acc[njp * 2 + 1], ah, bh4 + 2);
                mma16816(acc[njp * 2 + 1], ah, bl4 + 2);
                mma16816(acc[njp * 2 + 1], al, bh4 + 2);
                mma16816(acc[njp * 2 + 1], al, bl4 + 2);
            }
        }

        // fragment swap -> lane owns ONE row, 4 consecutive cols per nj
        // row-pair shared threshold: partner lane (l^2) owns the SAME row;
        // scores below the partner's 20th value cannot be in the row top-20.
        float thr = v[19];
        thr = fmaxf(thr, __shfl_xor_sync(0xffffffffu, thr, 2));
        const float* nxc = nxx + curb * 64;
#pragma unroll
        for (int nj = 0; nj < 8; ++nj) {
            float d0 = acc[nj][0], d1 = acc[nj][1], d2 = acc[nj][2], d3 = acc[nj][3];
            float r0 = __shfl_xor_sync(0xffffffffu, oddh ? d0 : d2, 1);
            float r1 = __shfl_xor_sync(0xffffffffu, oddh ? d1 : d3, 1);
            float c0 = oddh ? r0 : d0;
            float c1 = oddh ? r1 : d1;
            float c2 = oddh ? d2 : r0;
            float c3 = oddh ? d3 : r1;
            int jc = nj * 8 + colbase;
            float4 nx = *(const float4*)&nxc[jc];
            float s0 = fmaf(2.f, c0, nx.x);
            float s1 = fmaf(2.f, c1, nx.y);
            float s2 = fmaf(2.f, c2, nx.z);
            float s3 = fmaf(2.f, c3, nx.w);
            // group prefilter: only touch the push path if any of 4 beats thr
            float gmax = fmaxf(fmaxf(s0, s1), fmaxf(s2, s3));
            if (gmax > thr) {
                int j0 = ch * 64 + jc;
                if (s0 > thr) { pend_s[cnt] = s0; pend_j[cnt] = j0;     ++cnt; }
                if (s1 > thr) { pend_s[cnt] = s1; pend_j[cnt] = j0 + 1; ++cnt; }
                if (s2 > thr) { pend_s[cnt] = s2; pend_j[cnt] = j0 + 2; ++cnt; }
                if (s3 > thr) { pend_s[cnt] = s3; pend_j[cnt] = j0 + 3; ++cnt; }
            }
        }
        // batch drain (bounded: max 7 carried + 32 new < 40)
        if (cnt >= 8) {
            for (int u = 0; u < cnt; ++u) {
                float s = pend_s[u];
                if (s > v[19]) insert20(s, pend_j[u], v, ixr);
            }
            cnt = 0;
        }
    }
    // final drain
    for (int u = 0; u < cnt; ++u) {
        float s = pend_s[u];
        if (s > v[19]) insert20(s, pend_j[u], v, ixr);
    }

    __syncthreads();   // all MMA reads done -> overlay A (stv) and B (sti) regions
    {
        float* stv = (float*)sm;               // [128][43] floats (22016 B in A region)
        int*   sti = (int*)(sm + OFF_B);       // [128][43] ints  (22016 B in B region)
        int rloc = mrow0 + gid + 8 * (tig & 1);
        int half = tig >> 1;
        int base = rloc * 43 + half * 21;
#pragma unroll
        for (int q = 0; q < 20; ++q) { stv[base + q] = v[q]; sti[base + q] = ixr[q]; }
        stv[base + 20] = -3.4e38f;             // sentinel at 20 / 41
        __syncthreads();

        if (t < 128) {
            const float* a = stv + t * 43;
            const int*  ai = sti + t * 43;
            int ia = 0, ib = 21;
            int* dst = &g_idx[((size_t)b * NN + ibase + t) * KNN];
#pragma unroll
            for (int k = 0; k < KNN; ++k) {
                float va = a[ia], vb = a[ib];
                bool ta = va >= vb;
                dst[k] = ta ? ai[ia] : ai[ib];
                ia += ta;
                ib += !ta;
            }
        }
    }
}

// ---------------- kernel 5: gather-max + leaky + transposed write ------------
__global__ __launch_bounds__(256) void gathermax_kernel(float* __restrict__ out) {
    __shared__ int   sidx[32 * KNN];
    __shared__ float sres[32 * RESP];
    int b = blockIdx.y;
    int ibase = blockIdx.x * 32;
    int t = threadIdx.x;
    int w = t >> 5;
    int l = t & 31;

    for (int k = t; k < 32 * KNN; k += 256)
        sidx[k] = g_idx[((size_t)b * NN + ibase) * KNN + k];
    __syncthreads();

    const float* GTb = g_GT + (size_t)b * NN * OO;
    const float* HTb = g_HT + (size_t)b * NN * OO;

#pragma unroll
    for (int p = 0; p < 4; ++p) {
        int pp = w * 4 + p;
        int i = ibase + pp;
        float4 m = make_float4(-3.4e38f, -3.4e38f, -3.4e38f, -3.4e38f);
#pragma unroll
        for (int k = 0; k < KNN; ++k) {
            int j = sidx[pp * KNN + k];
            float4 g = *(const float4*)&GTb[(size_t)j * OO + l * 4];
            m.x = fmaxf(m.x, g.x); m.y = fmaxf(m.y, g.y);
            m.z = fmaxf(m.z, g.z); m.w = fmaxf(m.w, g.w);
        }
        float4 h = *(const float4*)&HTb[(size_t)i * OO + l * 4];
        float v0 = m.x + h.x, v1 = m.y + h.y, v2 = m.z + h.z, v3 = m.w + h.w;
        v0 = v0 >= 0.f ? v0 : 0.2f * v0;
        v1 = v1 >= 0.f ? v1 : 0.2f * v1;
        v2 = v2 >= 0.f ? v2 : 0.2f * v2;
        v3 = v3 >= 0.f ? v3 : 0.2f * v3;
        *(float4*)&sres[pp * RESP + l * 4] = make_float4(v0, v1, v2, v3);
    }
    __syncthreads();

    float* ob = out + (size_t)b * OO * NN;
    for (int k = t; k < OO * 32; k += 256) {
        int o = k >> 5, ii = k & 31;
        ob[(size_t)o * NN + ibase + ii] = sres[ii * RESP + o];
    }
}

// ---------------- launch ------------------------------------------------------
extern "C" void kernel_launch(void* const* d_in, const int* in_sizes, int n_in,
                              void* d_out, int out_size) {
    const float* x    = (const float*)d_in[0];   // (8, 64, 4096)
    const float* W    = (const float*)d_in[1];   // (128, 128)
    const float* bvec = (const float*)d_in[2];   // (128,)
    float* out = (float*)d_out;                  // (8, 128, 4096)

    const int SMEM_GEMM = (CC * 256 + CC * 64) * 4;   // 80KB
    cudaFuncSetAttribute(gemm_gh_kernel, cudaFuncAttributeMaxDynamicSharedMemorySize, SMEM_GEMM);
    cudaFuncSetAttribute(knn_kernel,     cudaFuncAttributeMaxDynamicSharedMemorySize, KNN_SMEM);

    split_kernel<<<dim3(NN / 64, BB), 256>>>(x);
    uprep_kernel<<<CC, 256>>>(W);
    gemm_gh_kernel<<<dim3(NN / 64, BB), 256, SMEM_GEMM>>>(x, bvec);
    knn_kernel<<<dim3(NN / 128, BB), 256, KNN_SMEM>>>();
    gathermax_kernel<<<dim3(NN / 32, BB), 256>>>(out);
}